// round 12
// baseline (speedup 1.0000x reference)
#include <cuda_runtime.h>
#include <math.h>
#include <stdint.h>

#define DK 256
#define DEMB 768
#define CH 32
#define TMAX 1000
#define PMAX 200
#define NCHS_MAX ((TMAX + CH - 1) / CH)   // 32
#define NCHP_MAX ((PMAX + CH - 1) / CH)   // 7

#define S_DECAY 0.95f
#define P_DECAY 0.99f
#define ALPHA   0.1f
#define BETA    1.0f
#define EPSN    1e-12f

// ---------------- device scratch ----------------
__device__ float g_K [TMAX*DK];
__device__ float g_Kn[TMAX*DK];
__device__ float g_V [TMAX*DK];
__device__ float g_PK[PMAX*DK];
__device__ float g_PV[PMAX*DK];
__device__ float g_W [(NCHS_MAX + 2*NCHP_MAX)*CH*DK];
// transposed scan-order tiles: [slot][col][CH]
__device__ float g_KT[(NCHS_MAX + 2*NCHP_MAX)*CH*DK];
__device__ float g_VT[(NCHS_MAX + NCHP_MAX)*CH*DK];
__device__ float g_c[NCHP_MAX*CH];
__device__ float g_res[4*DK];
__device__ int   g_bar1 = 0, g_bar2 = 0, g_done = 0;

// ---------------- helpers ----------------
__device__ __forceinline__ unsigned long long pack2(float lo, float hi) {
    unsigned long long r;
    asm("mov.b64 %0, {%1, %2};" : "=l"(r) : "f"(lo), "f"(hi));
    return r;
}
__device__ __forceinline__ unsigned long long fma2(unsigned long long a,
                                                   unsigned long long b,
                                                   unsigned long long c) {
    unsigned long long d;
    asm("fma.rn.f32x2 %0, %1, %2, %3;" : "=l"(d) : "l"(a), "l"(b), "l"(c));
    return d;
}
__device__ __forceinline__ void unpack2(unsigned long long v, float& lo, float& hi) {
    asm("mov.b64 {%0, %1}, %2;" : "=f"(lo), "=f"(hi) : "l"(v));
}
__device__ __forceinline__ uint32_t smem_u32(const void* p) {
    uint32_t a;
    asm("{ .reg .u64 t; cvta.to.shared.u64 t, %1; cvt.u32.u64 %0, t; }" : "=r"(a) : "l"(p));
    return a;
}
__device__ __forceinline__ void mbar_init(uint32_t a, uint32_t n) {
    asm volatile("mbarrier.init.shared.b64 [%0], %1;" :: "r"(a), "r"(n) : "memory");
}
__device__ __forceinline__ void mbar_expect(uint32_t a, uint32_t bytes) {
    asm volatile("mbarrier.arrive.expect_tx.shared.b64 _, [%0], %1;" :: "r"(a), "r"(bytes) : "memory");
}
__device__ __forceinline__ void bulk_g2s(uint32_t dst, const void* src, uint32_t bytes, uint32_t mbar) {
    asm volatile("cp.async.bulk.shared::cluster.global.mbarrier::complete_tx::bytes [%0], [%1], %2, [%3];"
                 :: "r"(dst), "l"(src), "r"(bytes), "r"(mbar) : "memory");
}
__device__ __forceinline__ void mbar_wait(uint32_t a, uint32_t parity) {
    asm volatile(
        "{\n\t.reg .pred P;\n"
        "W_%=:\n\t"
        "mbarrier.try_wait.parity.acquire.cta.shared::cta.b64 P, [%0], %1, 0x989680;\n\t"
        "@P bra.uni D_%=;\n\t"
        "bra.uni W_%=;\n"
        "D_%=:\n\t}"
        :: "r"(a), "r"(parity) : "memory");
}

// ---------------- phase 1: K/V projection (R8 verbatim — measured best) ----------------
#define ETILE 32
#define NSTAGE (DEMB / ETILE)     // 24
#define NBUF 3
#define WBUF_FLOATS (ETILE*DK*2)  // 16384 floats
#define EST_OFF (NBUF*WBUF_FLOATS)        // 49152
#define DYN_BYTES ((EST_OFF + DEMB*8) * 4)   // 221184 B

__device__ __forceinline__ void kv_phase(float* dynkv, unsigned long long* mb,
                     const float* __restrict__ emb,
                     const float* __restrict__ Wk, const float* __restrict__ bk,
                     const float* __restrict__ Wv, const float* __restrict__ bv,
                     int T)
{
    float* wbuf = dynkv;
    float* est  = dynkv + EST_OFF;

    const int tid = threadIdx.x;
    const int r0  = blockIdx.x * 8;
    const int rows = min(8, T - r0);
    const uint32_t wbufb = smem_u32(wbuf);
    const int s0 = blockIdx.x % NSTAGE;

    for (int idx = tid; idx < 8*DEMB; idx += 256) {
        int r = idx / DEMB, e = idx - r*DEMB;
        est[e*8 + r] = (r < rows) ? emb[(r0 + r)*DEMB + e] : 0.f;
    }
    if (tid == 0) {
        #pragma unroll
        for (int i = 0; i < NBUF; i++) mbar_init(smem_u32(&mb[i]), 1);
    }
    __syncthreads();

    auto issue = [&](int i) {
        int s = s0 + i; if (s >= NSTAGE) s -= NSTAGE;
        int buf = i % NBUF;
        uint32_t mba = smem_u32(&mb[buf]);
        uint32_t dst = wbufb + (uint32_t)buf * (WBUF_FLOATS*4u);
        mbar_expect(mba, WBUF_FLOATS*4u);
        bulk_g2s(dst,               Wk + s*ETILE*DK, ETILE*DK*4u, mba);
        bulk_g2s(dst + ETILE*DK*4u, Wv + s*ETILE*DK, ETILE*DK*4u, mba);
    };
    if (tid == 0) { issue(0); issue(1); issue(2); }

    unsigned long long aK[4], aV[4];
    #pragma unroll
    for (int p = 0; p < 4; p++) { aK[p] = pack2(0.f, 0.f); aV[p] = pack2(0.f, 0.f); }

    for (int i = 0; i < NSTAGE; i++) {
        int s = s0 + i; if (s >= NSTAGE) s -= NSTAGE;
        mbar_wait(smem_u32(&mb[i % NBUF]), (i / NBUF) & 1);
        const float* Wks = wbuf + (i % NBUF) * WBUF_FLOATS;
        const float* Wvs = Wks + ETILE*DK;
        const int e0 = s * ETILE;

        #pragma unroll 16
        for (int ee = 0; ee < ETILE; ee++) {
            float wk = Wks[ee*DK + tid];
            float wv = Wvs[ee*DK + tid];
            unsigned long long wk2 = pack2(wk, wk);
            unsigned long long wv2 = pack2(wv, wv);
            const float* ep = &est[(e0 + ee)*8];
            ulonglong2 p01 = *(const ulonglong2*)ep;
            ulonglong2 p23 = *(const ulonglong2*)(ep + 4);
            aK[0] = fma2(p01.x, wk2, aK[0]);  aV[0] = fma2(p01.x, wv2, aV[0]);
            aK[1] = fma2(p01.y, wk2, aK[1]);  aV[1] = fma2(p01.y, wv2, aV[1]);
            aK[2] = fma2(p23.x, wk2, aK[2]);  aV[2] = fma2(p23.x, wv2, aV[2]);
            aK[3] = fma2(p23.y, wk2, aK[3]);  aV[3] = fma2(p23.y, wv2, aV[3]);
        }
        __syncthreads();
        if (tid == 0 && i + NBUF < NSTAGE) issue(i + NBUF);
    }

    float bkv = bk[tid], bvv = bv[tid];
    #pragma unroll
    for (int p = 0; p < 4; p++) {
        float k0,k1,v0,v1;
        unpack2(aK[p], k0, k1);
        unpack2(aV[p], v0, v1);
        int r = 2*p;
        if (r < rows)     { g_K[(r0+r  )*DK + tid] = k0 + bkv; g_V[(r0+r  )*DK + tid] = v0 + bvv; }
        if (r + 1 < rows) { g_K[(r0+r+1)*DK + tid] = k1 + bkv; g_V[(r0+r+1)*DK + tid] = v1 + bvv; }
    }
}

// ---------------- phase 2: prep (+ transposed scan-order K/V tiles) ----------------
__device__ __forceinline__ void prep_phase(float* dyn, int cid,
                                           int T, int P, int nchS, int nchP)
{
    float* ks  = dyn;             // 32*260
    float* vs  = dyn + 8320;      // 32*260 (para only)
    float* Gs  = dyn + 16640;     // 32*33
    float* Ts  = dyn + 17696;     // 32*36
    float* Pm  = dyn + 18848;
    float* fs  = dyn + 18880;
    float* lfs = dyn + 18912;

    const int tid = threadIdx.x;
    const int wid = tid >> 5, lane = tid & 31;

    int type, chunk, steps;
    if (cid < nchS)              { type = 0; chunk = cid;               steps = T; }
    else if (cid < nchS + nchP)  { type = 1; chunk = cid - nchS;        steps = P; }
    else                         { type = 2; chunk = cid - nchS - nchP; steps = P; }
    const int lo  = chunk * CH;
    const int len = min(CH, steps - lo);
    const bool bwd = (type <= 1);
    const bool isPara = (type >= 1);

    if (!isPara) {
        #pragma unroll
        for (int u = 0; u < 8; u++) {
            int id = tid + 256*u;
            int a = id >> 6, c4 = (id & 63) * 4;
            float4 v = make_float4(0.f, 0.f, 0.f, 0.f);
            if (a < len) v = *(const float4*)&g_K[(lo + a)*DK + c4];
            *(float4*)&ks[a*260 + c4] = v;
        }
    } else {
        #pragma unroll
        for (int g = 0; g < 8; g++) {
            int r  = (tid >> 6) + 4*g;
            int c4 = (tid & 63) * 4;
            float4 ak = make_float4(0.f,0.f,0.f,0.f);
            float4 av = make_float4(0.f,0.f,0.f,0.f);
            if (r < len) {
                #pragma unroll
                for (int i = 0; i < 5; i++) {
                    float4 kk = *(const float4*)&g_K[((lo + r)*5 + i)*DK + c4];
                    float4 vv = *(const float4*)&g_V[((lo + r)*5 + i)*DK + c4];
                    ak.x += kk.x; ak.y += kk.y; ak.z += kk.z; ak.w += kk.w;
                    av.x += vv.x; av.y += vv.y; av.z += vv.z; av.w += vv.w;
                }
                ak.x *= 0.2f; ak.y *= 0.2f; ak.z *= 0.2f; ak.w *= 0.2f;
                av.x *= 0.2f; av.y *= 0.2f; av.z *= 0.2f; av.w *= 0.2f;
                if (type == 1) *(float4*)&g_PV[(lo + r)*DK + c4] = av;
            }
            *(float4*)&ks[r*260 + c4] = ak;
            *(float4*)&vs[r*260 + c4] = av;
        }
    }
    __syncthreads();

    if (type == 2) {
        #pragma unroll
        for (int rr = 0; rr < 4; rr++) {
            int r = wid*4 + rr;
            float s = 0.f;
            #pragma unroll
            for (int m = 0; m < 8; m++) s += vs[r*260 + lane + 32*m];
            #pragma unroll
            for (int o = 16; o; o >>= 1) s += __shfl_xor_sync(0xffffffffu, s, o);
            if (lane == 0) Pm[r] = s * (1.f/256.f);
        }
    }

    {
        float* gout = isPara ? g_PK : g_Kn;
        const bool wr = (type != 2);
        #pragma unroll
        for (int rr = 0; rr < 4; rr++) {
            int r = wid*4 + rr;
            float v[8]; float s = 0.f;
            #pragma unroll
            for (int m = 0; m < 8; m++) { v[m] = ks[r*260 + lane + 32*m]; s += v[m]*v[m]; }
            #pragma unroll
            for (int o = 16; o; o >>= 1) s += __shfl_xor_sync(0xffffffffu, s, o);
            float rinv = 1.f / fmaxf(sqrtf(s), EPSN);
            #pragma unroll
            for (int m = 0; m < 8; m++) {
                float nv = v[m] * rinv;
                ks[r*260 + lane + 32*m] = nv;
                if (wr && r < len) gout[(lo + r)*DK + lane + 32*m] = nv;
            }
        }
    }
    __syncthreads();

    {
        float acc[4] = {0.f, 0.f, 0.f, 0.f};
        #pragma unroll 8
        for (int i4 = 0; i4 < 64; i4++) {
            float4 own = *(const float4*)&ks[lane*260 + i4*4];
            #pragma unroll
            for (int s = 0; s < 4; s++) {
                float4 b = *(const float4*)&ks[(wid + 8*s)*260 + i4*4];
                acc[s] += own.x*b.x + own.y*b.y + own.z*b.z + own.w*b.w;
            }
        }
        #pragma unroll
        for (int s = 0; s < 4; s++) Gs[(wid + 8*s)*33 + lane] = acc[s];
    }
    __syncthreads();

    #pragma unroll
    for (int cc = 0; cc < 4; cc++) {
        int k = wid*4 + cc;
        float v = (lane == k) ? 1.f : 0.f;
        for (int i = 0; i < len; i++) {
            float vi = __shfl_sync(0xffffffffu, v, i);
            if (lane > i && lane < len) {
                float g = bwd ? Gs[(len-1-lane)*33 + (len-1-i)]
                              : Gs[lane*33 + i];
                v -= ALPHA * g * vi;
            }
        }
        Ts[lane*36 + k] = v;
    }
    __syncthreads();

    if (type == 2 && wid == 0) {
        float f = 0.f;
        if (lane < len) {
            float dp = 1.f;
            for (int i = 0; i <= lane; i++) dp *= (1.f / P_DECAY);
            f = BETA * dp * Pm[lane];
        }
        fs[lane] = f;
        __syncwarp();
        float lf = 0.f;
        if (lane < len)
            for (int i = 0; i < lane; i++) lf += Gs[lane*33 + i] * fs[i];
        lfs[lane] = lf;
        __syncwarp();
        float e = 0.f;
        #pragma unroll 8
        for (int k2 = 0; k2 < CH; k2++) e += Ts[lane*36 + k2] * lfs[k2];
        g_c[chunk*CH + lane] = -ALPHA * e + f;
    }

    // scan-order columns of Kn (ksv) — also store transposed tile g_KT
    float ksv[CH];
    #pragma unroll
    for (int m = 0; m < CH; m++) {
        int rl = bwd ? (len - 1 - m) : m;
        ksv[m] = (m < len) ? ks[rl*260 + tid] : 0.f;
    }
    {
        float* KTp = g_KT + ((size_t)cid*DK + tid)*CH;
        #pragma unroll
        for (int m4 = 0; m4 < 8; m4++)
            *(float4*)&KTp[m4*4] = make_float4(ksv[m4*4], ksv[m4*4+1], ksv[m4*4+2], ksv[m4*4+3]);
    }
    // transposed V tile for backward scans
    if (bwd) {
        float vsv[CH];
        #pragma unroll
        for (int m = 0; m < CH; m++) {
            int rl = len - 1 - m;
            float v = 0.f;
            if (m < len) v = (type == 0) ? g_V[(lo + rl)*DK + tid] : vs[rl*260 + tid];
            vsv[m] = v;
        }
        float* VTp = g_VT + ((size_t)cid*DK + tid)*CH;
        #pragma unroll
        for (int m4 = 0; m4 < 8; m4++)
            *(float4*)&VTp[m4*4] = make_float4(vsv[m4*4], vsv[m4*4+1], vsv[m4*4+2], vsv[m4*4+3]);
    }

    // W = T * K-chunk (scan order), for stage A
    float* Wout = g_W + (size_t)cid * CH * DK;
    #pragma unroll
    for (int j = 0; j < CH; j++) {
        float acc2 = 0.f;
        #pragma unroll
        for (int m4 = 0; m4 < 8; m4++) {
            float4 t = *(const float4*)&Ts[j*36 + m4*4];
            acc2 += t.x*ksv[m4*4] + t.y*ksv[m4*4+1] + t.z*ksv[m4*4+2] + t.w*ksv[m4*4+3];
        }
        Wout[j*DK + tid] = acc2;
    }
}

// ---------------- phase 3: scans (float4 loads) + final in block 0 ----------------
__device__ __forceinline__ float bred256(float x, float* red)
{
    const int tid = threadIdx.x;
    #pragma unroll
    for (int o = 16; o; o >>= 1) x += __shfl_xor_sync(0xffffffffu, x, o);
    __syncthreads();
    if ((tid & 31) == 0) red[tid >> 5] = x;
    __syncthreads();
    float s = 0.f;
    #pragma unroll
    for (int w = 0; w < 8; w++) s += red[w];
    return s;
}

__device__ __forceinline__ void scan_phase(float* dyn, int bid,
                                           const float* __restrict__ q,
                                           float* __restrict__ out,
                                           int T, int P, int nchS, int nchP)
{
    float* a_s    = dyn;            // 256 (16B aligned)
    float* sigk_s = dyn + 256;
    float* sigv_s = dyn + 288;
    float* dpow   = dyn + 320;
    float* red    = dyn + 356;
    float* s_invp = dyn + 364;

    const int tid = threadIdx.x;
    const int wid = tid >> 5, lane = tid & 31;
    const bool fwd  = (bid == 3);
    const bool sent = (bid == 0);
    const bool hasV = !fwd;
    const float decay = sent ? S_DECAY : P_DECAY;
    const int nch   = sent ? nchS : nchP;
    const int steps = sent ? T : P;
    const int slot0 = sent ? 0 : (fwd ? (nchS + nchP) : nchS);

    if (tid == 0) {
        dpow[0] = 1.f;
        for (int i = 0; i < CH; i++) dpow[i+1] = dpow[i] * decay;
    }
    __syncthreads();

    float qv = q[tid];
    {
        float x = qv * qv;
        #pragma unroll
        for (int o = 16; o; o >>= 1) x += __shfl_xor_sync(0xffffffffu, x, o);
        if (lane == 0) red[wid] = x;
        __syncthreads();
        if (tid == 0) {
            float s = 0.f;
            #pragma unroll
            for (int w = 0; w < 8; w++) s += red[w];
            *s_invp = 1.f / fmaxf(sqrtf(s), EPSN);
        }
        __syncthreads();
    }
    float s_inv = *s_invp;
    float a;
    if (bid <= 1)      a = qv * s_inv;
    else if (bid == 2) a = 1.f/256.f;
    else               a = 0.f;
    a_s[tid] = a;

    const int j0 = wid * 4;
    float4 wq[4][2];
    float creg[4] = {0.f, 0.f, 0.f, 0.f};

    {   // prefetch FIRST SCAN CHUNK's W rows + c  (bugfix: include the chunk offset)
        int chunk0 = fwd ? 0 : (nch - 1);
        const float* Wp = g_W + (size_t)(slot0 + chunk0) * CH * DK;
        #pragma unroll
        for (int r = 0; r < 4; r++) {
            const float* row = Wp + (j0 + r)*DK + lane*8;
            wq[r][0] = *(const float4*)row;
            wq[r][1] = *(const float4*)(row + 4);
        }
        if (fwd) {
            #pragma unroll
            for (int r = 0; r < 4; r++) creg[r] = g_c[chunk0*CH + j0 + r];
        }
    }

    float outreg = 0.f;

    for (int c = 0; c < nch; c++) {
        const int chunk = fwd ? c : (nch - 1 - c);
        const int slot  = slot0 + chunk;
        const int len = min(CH, steps - chunk*CH);
        __syncthreads();   // a_s published; sig buffers free

        // transposed, scan-ordered, zero-padded tiles: 8 LDG.128 each
        float kreg[CH], vreg[CH];
        {
            const float4* KTp = (const float4*)(g_KT + ((size_t)slot*DK + tid)*CH);
            #pragma unroll
            for (int m4 = 0; m4 < 8; m4++) {
                float4 kk = KTp[m4];
                kreg[m4*4] = kk.x; kreg[m4*4+1] = kk.y; kreg[m4*4+2] = kk.z; kreg[m4*4+3] = kk.w;
            }
            if (hasV) {
                const float4* VTp = (const float4*)(g_VT + ((size_t)slot*DK + tid)*CH);
                #pragma unroll
                for (int m4 = 0; m4 < 8; m4++) {
                    float4 vv = VTp[m4];
                    vreg[m4*4] = vv.x; vreg[m4*4+1] = vv.y; vreg[m4*4+2] = vv.z; vreg[m4*4+3] = vv.w;
                }
            }
        }

        // stage A: b_j = W[j] . a  (lane owns 8 consecutive columns)
        float4 a0 = *(const float4*)&a_s[lane*8];
        float4 a1 = *(const float4*)&a_s[lane*8 + 4];
        float s[4];
        #pragma unroll
        for (int r = 0; r < 4; r++) {
            float t = wq[r][0].x*a0.x + wq[r][0].y*a0.y + wq[r][0].z*a0.z + wq[r][0].w*a0.w
                    + wq[r][1].x*a1.x + wq[r][1].y*a1.y + wq[r][1].z*a1.z + wq[r][1].w*a1.w;
            s[r] = t;
        }
        #pragma unroll
        for (int o = 16; o; o >>= 1)
            #pragma unroll
            for (int r = 0; r < 4; r++)
                s[r] += __shfl_xor_sync(0xffffffffu, s[r], o);
        if (lane == 0) {
            #pragma unroll
            for (int r = 0; r < 4; r++) {
                int j = j0 + r;
                float sk = 0.f, sv = 0.f;
                if (j < len) {
                    if (fwd) { sk = -ALPHA * s[r] + creg[r]; }
                    else     { sk = -ALPHA * s[r]; sv = BETA * dpow[j] * s[r]; }
                }
                sigk_s[j] = sk;
                sigv_s[j] = sv;
            }
        }

        // prefetch next chunk's W (+c)
        if (c + 1 < nch) {
            int nchunk = fwd ? (c + 1) : (nch - 2 - c);
            const float* Wp = g_W + (size_t)(slot0 + nchunk) * CH * DK;
            #pragma unroll
            for (int r = 0; r < 4; r++) {
                const float* row = Wp + (j0 + r)*DK + lane*8;
                wq[r][0] = *(const float4*)row;
                wq[r][1] = *(const float4*)(row + 4);
            }
            if (fwd) {
                #pragma unroll
                for (int r = 0; r < 4; r++) creg[r] = g_c[nchunk*CH + j0 + r];
            }
        }
        __syncthreads();   // sig ready

        // stage B: rank updates (register resident, padded rows are zero)
        float wsum = 0.f, osum = 0.f;
        #pragma unroll
        for (int j = 0; j < CH; j++) {
            wsum += sigk_s[j] * kreg[j];
            if (hasV) osum += sigv_s[j] * vreg[j];
        }
        outreg += osum;
        a = dpow[len] * (a + wsum);
        a_s[tid] = a;
    }

    if (bid != 0) {
        if (bid < 3) g_res[bid*DK + tid] = outreg;
        else         g_res[3*DK + tid]   = a;
        __threadfence();
        __syncthreads();
        if (tid == 0) atomicAdd(&g_done, 1);
        return;
    }

    // block 0: wait + final combine
    if (tid == 0) { while (*(volatile int*)&g_done < 3) { } }
    __threadfence();
    __syncthreads();

    float r1  = g_res[1*DK + tid];
    float r2  = g_res[2*DK + tid];
    float dkv = g_res[3*DK + tid];
    float ssd = bred256(dkv*dkv, red);
    float dot = bred256(qv*dkv, red);
    float coef = dot * s_inv / fmaxf(sqrtf(ssd), EPSN);
    out[tid] = 0.2f*outreg + 0.3f*r1 + 0.5f*(BETA*coef)*r2;

    __syncthreads();
    if (tid == 0) { g_bar1 = 0; g_bar2 = 0; g_done = 0; }
}

// ---------------- the single fused kernel ----------------
__global__ void __launch_bounds__(256, 1) k_mega(
                     const float* __restrict__ emb, const float* __restrict__ q,
                     const float* __restrict__ Wk, const float* __restrict__ bk,
                     const float* __restrict__ Wv, const float* __restrict__ bv,
                     float* __restrict__ out,
                     int T, int P, int nchS, int nchP, int nKV, int nPrep)
{
    extern __shared__ __align__(16) float dyn[];
    __shared__ __align__(8) unsigned long long mb[NBUF];

    const int bid = blockIdx.x, tid = threadIdx.x;

    kv_phase(dyn, mb, emb, Wk, bk, Wv, bv, T);

    __threadfence();
    __syncthreads();
    if (tid == 0) atomicAdd(&g_bar1, 1);
    if (bid >= nPrep) return;
    if (tid == 0) { while (*(volatile int*)&g_bar1 < nKV) { } }
    __threadfence();
    __syncthreads();

    prep_phase(dyn, bid, T, P, nchS, nchP);

    __threadfence();
    __syncthreads();
    if (tid == 0) atomicAdd(&g_bar2, 1);
    if (bid >= 4) return;
    if (tid == 0) { while (*(volatile int*)&g_bar2 < nPrep) { } }
    __threadfence();
    __syncthreads();

    scan_phase(dyn, bid, q, out, T, P, nchS, nchP);
}

// ---------------- launcher ----------------
extern "C" void kernel_launch(void* const* d_in, const int* in_sizes, int n_in,
                              void* d_out, int out_size)
{
    const float* emb = (const float*)d_in[0];
    const float* q   = (const float*)d_in[1];
    const float* Wk  = (const float*)d_in[2];
    const float* bk  = (const float*)d_in[3];
    const float* Wv  = (const float*)d_in[4];
    const float* bv  = (const float*)d_in[5];
    // d_in[6..8] = zero initial memories (collapsed analytically)

    int T = in_sizes[0] / DEMB;     // 1000
    int P = T / 5;                  // 200
    int nchS = (T + CH - 1) / CH;   // 32
    int nchP = (P + CH - 1) / CH;   // 7
    int nKV  = (T + 7) / 8;         // 125 (single wave)
    int nPrep = nchS + 2*nchP;      // 46

    cudaFuncSetAttribute(k_mega, cudaFuncAttributeMaxDynamicSharedMemorySize, DYN_BYTES);

    k_mega<<<nKV, 256, DYN_BYTES>>>(emb, q, Wk, bk, Wv, bv, (float*)d_out,
                                    T, P, nchS, nchP, nKV, nPrep);
}

// round 14
// speedup vs baseline: 1.4673x; 1.4673x over previous
#include <cuda_runtime.h>
#include <math.h>
#include <stdint.h>

#define DK 256
#define DEMB 768
#define CH 32
#define TMAX 1000
#define PMAX 200
#define NCHS_MAX ((TMAX + CH - 1) / CH)   // 32
#define NCHP_MAX ((PMAX + CH - 1) / CH)   // 7

#define S_DECAY 0.95f
#define P_DECAY 0.99f
#define ALPHA   0.1f
#define BETA    1.0f
#define EPSN    1e-12f

// ---------------- device scratch ----------------
__device__ float g_K [TMAX*DK];   // raw K
__device__ float g_Kn[TMAX*DK];   // normalized K
__device__ float g_V [TMAX*DK];   // raw V
__device__ float g_PK[PMAX*DK];   // normalized PK
__device__ float g_PV[PMAX*DK];   // raw PV
__device__ float g_W[(NCHS_MAX + 2*NCHP_MAX)*CH*DK];
__device__ float g_c[NCHP_MAX*CH];
__device__ float g_res[4*DK];

// ---------------- helpers ----------------
__device__ __forceinline__ uint32_t f2tf32(float x) {
    uint32_t u;
    asm("cvt.rna.tf32.f32 %0, %1;" : "=r"(u) : "f"(x));
    return u;
}
__device__ __forceinline__ void mma_tf32(float c[4],
                                         uint32_t a0, uint32_t a1, uint32_t a2, uint32_t a3,
                                         uint32_t b0, uint32_t b1) {
    asm volatile(
        "mma.sync.aligned.m16n8k8.row.col.f32.tf32.tf32.f32 "
        "{%0,%1,%2,%3}, {%4,%5,%6,%7}, {%8,%9}, {%0,%1,%2,%3};"
        : "+f"(c[0]), "+f"(c[1]), "+f"(c[2]), "+f"(c[3])
        : "r"(a0), "r"(a1), "r"(a2), "r"(a3), "r"(b0), "r"(b1));
}

// ---------------- kernel 1: K/V projection via mma.sync tf32 (hi/lo split) ----------------
// Block = 64 emb rows x 64 output cols. Grid = 16 row-tiles x (4 K col-tiles + 4 V) = 128.
// D = Ah*Bh + Ah*Bl + Al*Bh, fp32 accumulation in tensor-core fragments.
#define KV_MT 64
#define KV_NT 64
#define KV_KC 32

__global__ void __launch_bounds__(256) k_kv(const float* __restrict__ emb,
                     const float* __restrict__ Wk, const float* __restrict__ bk,
                     const float* __restrict__ Wv, const float* __restrict__ bv,
                     int T)
{
    __shared__ uint32_t Ah[KV_MT][33], Al[KV_MT][33];   // 64 rows x 32 k (pad 33)
    __shared__ uint32_t Bh[KV_KC][65], Bl[KV_KC][65];   // 32 k x 64 n (pad 65)

    const int tid  = threadIdx.x;
    const int wid  = tid >> 5, lane = tid & 31;
    const int g    = lane >> 2;        // groupID 0..7
    const int tig  = lane & 3;         // threadID-in-group 0..3
    const int rt   = blockIdx.x >> 3;  // row tile
    const int nt   = blockIdx.x & 7;
    const bool isK = (nt < 4);
    const float* Wsel = isK ? Wk : Wv;
    const int c0   = (nt & 3) * KV_NT; // col offset within 256
    const int m0   = rt * KV_MT;
    const int mband = wid & 3;         // 4 m-bands of 16 rows
    const int nhalf = wid >> 2;        // 2 n-halves of 32 cols

    float acc[4][4];
    #pragma unroll
    for (int nf = 0; nf < 4; nf++)
        #pragma unroll
        for (int i = 0; i < 4; i++) acc[nf][i] = 0.f;

    for (int kc = 0; kc < DEMB; kc += KV_KC) {
        // stage A chunk (64 x 32), hi/lo tf32
        #pragma unroll
        for (int it = 0; it < 8; it++) {
            int idx = tid + 256*it;
            int r = idx >> 5, k = idx & 31;
            float x = 0.f;
            if (m0 + r < T) x = emb[(size_t)(m0 + r)*DEMB + kc + k];
            uint32_t hb = f2tf32(x);
            float hv = __uint_as_float(hb);
            uint32_t lb = f2tf32(x - hv);
            Ah[r][k] = hb;
            Al[r][k] = lb;
        }
        // stage B chunk (32 x 64), hi/lo tf32;  B[k][n] = Wsel[kc+k][c0+n]
        #pragma unroll
        for (int it = 0; it < 8; it++) {
            int idx = tid + 256*it;
            int k = idx >> 6, n = idx & 63;
            float x = Wsel[(size_t)(kc + k)*DK + c0 + n];
            uint32_t hb = f2tf32(x);
            float hv = __uint_as_float(hb);
            uint32_t lb = f2tf32(x - hv);
            Bh[k][n] = hb;
            Bl[k][n] = lb;
        }
        __syncthreads();

        #pragma unroll
        for (int ks = 0; ks < 4; ks++) {
            const int kk = ks * 8;
            const int ar0 = mband*16 + g;
            // A fragments (m16n8k8 tf32 row-major layout)
            uint32_t ah0 = Ah[ar0    ][kk + tig];
            uint32_t ah1 = Ah[ar0 + 8][kk + tig];
            uint32_t ah2 = Ah[ar0    ][kk + tig + 4];
            uint32_t ah3 = Ah[ar0 + 8][kk + tig + 4];
            uint32_t al0 = Al[ar0    ][kk + tig];
            uint32_t al1 = Al[ar0 + 8][kk + tig];
            uint32_t al2 = Al[ar0    ][kk + tig + 4];
            uint32_t al3 = Al[ar0 + 8][kk + tig + 4];
            #pragma unroll
            for (int nf = 0; nf < 4; nf++) {
                const int nb = nhalf*32 + nf*8;
                uint32_t bh0 = Bh[kk + tig    ][nb + g];
                uint32_t bh1 = Bh[kk + tig + 4][nb + g];
                uint32_t bl0 = Bl[kk + tig    ][nb + g];
                uint32_t bl1 = Bl[kk + tig + 4][nb + g];
                mma_tf32(acc[nf], ah0, ah1, ah2, ah3, bh0, bh1);
                mma_tf32(acc[nf], ah0, ah1, ah2, ah3, bl0, bl1);
                mma_tf32(acc[nf], al0, al1, al2, al3, bh0, bh1);
            }
        }
        __syncthreads();
    }

    // epilogue: fragment -> global (+bias). c0/c1: row g; c2/c3: row g+8; cols tig*2, tig*2+1
    const float* bsel = isK ? bk : bv;
    float* osel = isK ? g_K : g_V;
    const int mrow = m0 + mband*16;
    #pragma unroll
    for (int nf = 0; nf < 4; nf++) {
        int col = c0 + nhalf*32 + nf*8 + tig*2;
        float b0 = bsel[col], b1 = bsel[col + 1];
        int r0 = mrow + g, r1 = mrow + g + 8;
        if (r0 < T) {
            osel[(size_t)r0*DK + col]     = acc[nf][0] + b0;
            osel[(size_t)r0*DK + col + 1] = acc[nf][1] + b1;
        }
        if (r1 < T) {
            osel[(size_t)r1*DK + col]     = acc[nf][2] + b0;
            osel[(size_t)r1*DK + col + 1] = acc[nf][3] + b1;
        }
    }
}

// ---------------- kernel 2: prep (verbatim measured-good) ----------------
__global__ void __launch_bounds__(256) k_prep(int T, int P, int nchS, int nchP)
{
    extern __shared__ __align__(16) float dyn[];
    float* ks = dyn;            // 32*260
    float* vs = dyn + 8320;     // 32*260 (para only)
    __shared__ float Gs[CH*33];
    __shared__ __align__(16) float Ts[CH*36];
    __shared__ float Pm[CH];
    __shared__ float fs[CH], lfs[CH];

    const int cid = blockIdx.x, tid = threadIdx.x;
    const int wid = tid >> 5, lane = tid & 31;

    int type, chunk, steps;
    if (cid < nchS)              { type = 0; chunk = cid;               steps = T; }
    else if (cid < nchS + nchP)  { type = 1; chunk = cid - nchS;        steps = P; }
    else                         { type = 2; chunk = cid - nchS - nchP; steps = P; }
    const int lo  = chunk * CH;
    const int len = min(CH, steps - lo);
    const bool bwd = (type <= 1);
    const bool isPara = (type >= 1);

    if (!isPara) {
        #pragma unroll
        for (int u = 0; u < 8; u++) {
            int id = tid + 256*u;
            int a = id >> 6, c4 = (id & 63) * 4;
            float4 v = make_float4(0.f, 0.f, 0.f, 0.f);
            if (a < len) v = *(const float4*)&g_K[(lo + a)*DK + c4];
            *(float4*)&ks[a*260 + c4] = v;
        }
    } else {
        #pragma unroll
        for (int g = 0; g < 8; g++) {
            int r  = (tid >> 6) + 4*g;
            int c4 = (tid & 63) * 4;
            float4 ak = make_float4(0.f,0.f,0.f,0.f);
            float4 av = make_float4(0.f,0.f,0.f,0.f);
            if (r < len) {
                #pragma unroll
                for (int i = 0; i < 5; i++) {
                    float4 kk = *(const float4*)&g_K[((lo + r)*5 + i)*DK + c4];
                    float4 vv = *(const float4*)&g_V[((lo + r)*5 + i)*DK + c4];
                    ak.x += kk.x; ak.y += kk.y; ak.z += kk.z; ak.w += kk.w;
                    av.x += vv.x; av.y += vv.y; av.z += vv.z; av.w += vv.w;
                }
                ak.x *= 0.2f; ak.y *= 0.2f; ak.z *= 0.2f; ak.w *= 0.2f;
                av.x *= 0.2f; av.y *= 0.2f; av.z *= 0.2f; av.w *= 0.2f;
                if (type == 1) *(float4*)&g_PV[(lo + r)*DK + c4] = av;
            }
            *(float4*)&ks[r*260 + c4] = ak;
            *(float4*)&vs[r*260 + c4] = av;
        }
    }
    __syncthreads();

    if (type == 2) {
        #pragma unroll
        for (int rr = 0; rr < 4; rr++) {
            int r = wid*4 + rr;
            float s = 0.f;
            #pragma unroll
            for (int m = 0; m < 8; m++) s += vs[r*260 + lane + 32*m];
            #pragma unroll
            for (int o = 16; o; o >>= 1) s += __shfl_xor_sync(0xffffffffu, s, o);
            if (lane == 0) Pm[r] = s * (1.f/256.f);
        }
    }

    {
        float* gout = isPara ? g_PK : g_Kn;
        const bool wr = (type != 2);
        #pragma unroll
        for (int rr = 0; rr < 4; rr++) {
            int r = wid*4 + rr;
            float v[8]; float s = 0.f;
            #pragma unroll
            for (int m = 0; m < 8; m++) { v[m] = ks[r*260 + lane + 32*m]; s += v[m]*v[m]; }
            #pragma unroll
            for (int o = 16; o; o >>= 1) s += __shfl_xor_sync(0xffffffffu, s, o);
            float rinv = 1.f / fmaxf(sqrtf(s), EPSN);
            #pragma unroll
            for (int m = 0; m < 8; m++) {
                float nv = v[m] * rinv;
                ks[r*260 + lane + 32*m] = nv;
                if (wr && r < len) gout[(lo + r)*DK + lane + 32*m] = nv;
            }
        }
    }
    __syncthreads();

    {
        float acc[4] = {0.f, 0.f, 0.f, 0.f};
        #pragma unroll 8
        for (int i4 = 0; i4 < 64; i4++) {
            float4 own = *(const float4*)&ks[lane*260 + i4*4];
            #pragma unroll
            for (int s = 0; s < 4; s++) {
                float4 b = *(const float4*)&ks[(wid + 8*s)*260 + i4*4];
                acc[s] += own.x*b.x + own.y*b.y + own.z*b.z + own.w*b.w;
            }
        }
        #pragma unroll
        for (int s = 0; s < 4; s++) Gs[(wid + 8*s)*33 + lane] = acc[s];
    }
    __syncthreads();

    #pragma unroll
    for (int cc = 0; cc < 4; cc++) {
        int k = wid*4 + cc;
        float v = (lane == k) ? 1.f : 0.f;
        for (int i = 0; i < len; i++) {
            float vi = __shfl_sync(0xffffffffu, v, i);
            if (lane > i && lane < len) {
                float g = bwd ? Gs[(len-1-lane)*33 + (len-1-i)]
                              : Gs[lane*33 + i];
                v -= ALPHA * g * vi;
            }
        }
        Ts[lane*36 + k] = v;
    }
    __syncthreads();

    if (type == 2 && wid == 0) {
        float f = 0.f;
        if (lane < len) {
            float dp = 1.f;
            for (int i = 0; i <= lane; i++) dp *= (1.f / P_DECAY);
            f = BETA * dp * Pm[lane];
        }
        fs[lane] = f;
        __syncwarp();
        float lf = 0.f;
        if (lane < len)
            for (int i = 0; i < lane; i++) lf += Gs[lane*33 + i] * fs[i];
        lfs[lane] = lf;
        __syncwarp();
        float e = 0.f;
        #pragma unroll 8
        for (int k2 = 0; k2 < CH; k2++) e += Ts[lane*36 + k2] * lfs[k2];
        g_c[chunk*CH + lane] = -ALPHA * e + f;
    }

    float ksv[CH];
    #pragma unroll
    for (int m = 0; m < CH; m++) {
        int rl = bwd ? (len - 1 - m) : m;
        ksv[m] = (m < len) ? ks[rl*260 + tid] : 0.f;
    }
    float* Wout = g_W + (size_t)cid * CH * DK;
    #pragma unroll
    for (int j = 0; j < CH; j++) {
        float acc2 = 0.f;
        #pragma unroll
        for (int m4 = 0; m4 < 8; m4++) {
            float4 t = *(const float4*)&Ts[j*36 + m4*4];
            acc2 += t.x*ksv[m4*4] + t.y*ksv[m4*4+1] + t.z*ksv[m4*4+2] + t.w*ksv[m4*4+3];
        }
        Wout[j*DK + tid] = acc2;
    }
}

// ---------------- kernel 3: chunked probe scans (verbatim measured-good) ----------------
__global__ void __launch_bounds__(256) k_scan(const float* __restrict__ q,
                                              int T, int P, int nchS, int nchP)
{
    __shared__ float a_s[DK];
    __shared__ float sigk_s[CH], sigv_s[CH];
    __shared__ float dpow[CH+1];
    __shared__ float red[8];
    __shared__ float s_inv;

    const int bid = blockIdx.x, tid = threadIdx.x;
    const int wid = tid >> 5, lane = tid & 31;
    const bool fwd  = (bid == 3);
    const bool sent = (bid == 0);
    const float decay = sent ? S_DECAY : P_DECAY;
    const int nch   = sent ? nchS : nchP;
    const int steps = sent ? T : P;
    const float* Kd = sent ? g_Kn : g_PK;
    const float* Vd = sent ? g_V  : g_PV;
    const int slot0 = sent ? 0 : (fwd ? (nchS + nchP) : nchS);

    if (tid == 0) {
        dpow[0] = 1.f;
        for (int i = 0; i < CH; i++) dpow[i+1] = dpow[i] * decay;
    }

    float a;
    if (bid <= 1) {
        float qv = q[tid];
        float x = qv * qv;
        #pragma unroll
        for (int o = 16; o; o >>= 1) x += __shfl_xor_sync(0xffffffffu, x, o);
        if (lane == 0) red[wid] = x;
        __syncthreads();
        if (tid == 0) {
            float s = 0.f;
            #pragma unroll
            for (int w = 0; w < 8; w++) s += red[w];
            s_inv = 1.f / fmaxf(sqrtf(s), EPSN);
        }
        __syncthreads();
        a = qv * s_inv;
    } else {
        a = (bid == 2) ? (1.f/256.f) : 0.f;
    }
    a_s[tid] = a;

    const int j0 = wid * 4;
    float wreg[4][8];
    float creg[4] = {0.f, 0.f, 0.f, 0.f};

    {
        int chunk = fwd ? 0 : (nch - 1);
        const float* Wp = g_W + (size_t)(slot0 + chunk) * CH * DK;
        #pragma unroll
        for (int r = 0; r < 4; r++)
            #pragma unroll
            for (int m = 0; m < 8; m++)
                wreg[r][m] = Wp[(j0 + r)*DK + lane + 32*m];
        if (fwd) {
            #pragma unroll
            for (int r = 0; r < 4; r++) creg[r] = g_c[chunk*CH + j0 + r];
        }
    }

    float outreg = 0.f;

    for (int c = 0; c < nch; c++) {
        const int chunk = fwd ? c : (nch - 1 - c);
        const int lo  = chunk * CH;
        const int len = min(CH, steps - lo);
        const int hi  = lo + len - 1;
        __syncthreads();

        float kreg[CH], vreg[CH];
        #pragma unroll
        for (int j = 0; j < CH; j++) {
            int row = fwd ? (lo + j) : (hi - j);
            row = max(0, min(row, steps - 1));
            kreg[j] = Kd[row*DK + tid];
            vreg[j] = fwd ? 0.f : Vd[row*DK + tid];
        }

        float av[8];
        #pragma unroll
        for (int m = 0; m < 8; m++) av[m] = a_s[lane + 32*m];
        float s[4];
        #pragma unroll
        for (int r = 0; r < 4; r++) {
            float t = 0.f;
            #pragma unroll
            for (int m = 0; m < 8; m++) t += wreg[r][m] * av[m];
            s[r] = t;
        }
        #pragma unroll
        for (int o = 16; o; o >>= 1)
            #pragma unroll
            for (int r = 0; r < 4; r++)
                s[r] += __shfl_xor_sync(0xffffffffu, s[r], o);
        if (lane == 0) {
            #pragma unroll
            for (int r = 0; r < 4; r++) {
                int j = j0 + r;
                float sk = 0.f, sv = 0.f;
                if (j < len) {
                    if (fwd) { sk = -ALPHA * s[r] + creg[r]; }
                    else     { sk = -ALPHA * s[r]; sv = BETA * dpow[j] * s[r]; }
                }
                sigk_s[j] = sk;
                sigv_s[j] = sv;
            }
        }

        if (c + 1 < nch) {
            int nchunk = fwd ? (c + 1) : (nch - 2 - c);
            const float* Wp = g_W + (size_t)(slot0 + nchunk) * CH * DK;
            #pragma unroll
            for (int r = 0; r < 4; r++)
                #pragma unroll
                for (int m = 0; m < 8; m++)
                    wreg[r][m] = Wp[(j0 + r)*DK + lane + 32*m];
            if (fwd) {
                #pragma unroll
                for (int r = 0; r < 4; r++) creg[r] = g_c[nchunk*CH + j0 + r];
            }
        }
        __syncthreads();

        float wsum = 0.f, osum = 0.f;
        #pragma unroll
        for (int j = 0; j < CH; j++) {
            wsum += sigk_s[j] * kreg[j];
            osum += sigv_s[j] * vreg[j];
        }
        outreg += osum;
        a = dpow[len] * (a + wsum);
        a_s[tid] = a;
    }

    if (bid < 3) g_res[bid*DK + tid] = outreg;
    else         g_res[3*DK + tid]   = a;
}

// ---------------- kernel 4: combine (verbatim) ----------------
__device__ __forceinline__ float bred256(float x, float* red)
{
    const int tid = threadIdx.x;
    #pragma unroll
    for (int o = 16; o; o >>= 1) x += __shfl_xor_sync(0xffffffffu, x, o);
    __syncthreads();
    if ((tid & 31) == 0) red[tid >> 5] = x;
    __syncthreads();
    float s = 0.f;
    #pragma unroll
    for (int w = 0; w < 8; w++) s += red[w];
    return s;
}

__global__ void k_final(const float* __restrict__ q, float* __restrict__ out)
{
    __shared__ float red[8];
    const int tid = threadIdx.x;
    float qv  = q[tid];
    float dkv = g_res[3*256 + tid];
    float ssq = bred256(qv*qv, red);
    float ssd = bred256(dkv*dkv, red);
    float dot = bred256(qv*dkv, red);
    float coef = dot / (fmaxf(sqrtf(ssq), EPSN) * fmaxf(sqrtf(ssd), EPSN));
    out[tid] = 0.2f*g_res[tid] + 0.3f*g_res[256 + tid]
             + 0.5f * (BETA * coef) * g_res[512 + tid];
}

// ---------------- launcher ----------------
extern "C" void kernel_launch(void* const* d_in, const int* in_sizes, int n_in,
                              void* d_out, int out_size)
{
    const float* emb = (const float*)d_in[0];
    const float* q   = (const float*)d_in[1];
    const float* Wk  = (const float*)d_in[2];
    const float* bk  = (const float*)d_in[3];
    const float* Wv  = (const float*)d_in[4];
    const float* bv  = (const float*)d_in[5];
    // d_in[6..8] = zero initial memories (collapsed analytically)

    int T = in_sizes[0] / DEMB;     // 1000
    int P = T / 5;                  // 200
    int nchS = (T + CH - 1) / CH;   // 32
    int nchP = (P + CH - 1) / CH;   // 7
    int nRT  = (T + KV_MT - 1) / KV_MT;   // 16

    cudaFuncSetAttribute(k_prep, cudaFuncAttributeMaxDynamicSharedMemorySize, 16640*4);

    k_kv  <<<nRT*8, 256>>>(emb, Wk, bk, Wv, bv, T);
    k_prep<<<nchS + 2*nchP, 256, 16640*4>>>(T, P, nchS, nchP);
    k_scan<<<4, 256>>>(q, T, P, nchS, nchP);
    k_final<<<1, 256>>>(q, (float*)d_out);
}

// round 15
// speedup vs baseline: 1.8522x; 1.2623x over previous
#include <cuda_runtime.h>
#include <math.h>
#include <stdint.h>

#define DK 256
#define DEMB 768
#define CH 32
#define TMAX 1000
#define PMAX 200
#define NCHS_MAX ((TMAX + CH - 1) / CH)   // 32
#define NCHP_MAX ((PMAX + CH - 1) / CH)   // 7

#define S_DECAY 0.95f
#define P_DECAY 0.99f
#define ALPHA   0.1f
#define BETA    1.0f
#define EPSN    1e-12f

// ---------------- device scratch ----------------
__device__ float g_K [TMAX*DK];
__device__ float g_Kn[TMAX*DK];
__device__ float g_V [TMAX*DK];
__device__ float g_PK[PMAX*DK];
__device__ float g_PV[PMAX*DK];
__device__ float g_W[(NCHS_MAX + 2*NCHP_MAX)*CH*DK];
__device__ float g_c[NCHP_MAX*CH];
__device__ float g_res[4*DK];
__device__ int   g_kvdone[128];          // per-kv-block completion flags (zero-init)
__device__ int   g_bar2 = 0, g_done = 0;

// ---------------- helpers ----------------
__device__ __forceinline__ unsigned long long pack2(float lo, float hi) {
    unsigned long long r;
    asm("mov.b64 %0, {%1, %2};" : "=l"(r) : "f"(lo), "f"(hi));
    return r;
}
__device__ __forceinline__ unsigned long long fma2(unsigned long long a,
                                                   unsigned long long b,
                                                   unsigned long long c) {
    unsigned long long d;
    asm("fma.rn.f32x2 %0, %1, %2, %3;" : "=l"(d) : "l"(a), "l"(b), "l"(c));
    return d;
}
__device__ __forceinline__ void unpack2(unsigned long long v, float& lo, float& hi) {
    asm("mov.b64 {%0, %1}, %2;" : "=f"(lo), "=f"(hi) : "l"(v));
}
__device__ __forceinline__ uint32_t smem_u32(const void* p) {
    uint32_t a;
    asm("{ .reg .u64 t; cvta.to.shared.u64 t, %1; cvt.u32.u64 %0, t; }" : "=r"(a) : "l"(p));
    return a;
}
__device__ __forceinline__ void mbar_init(uint32_t a, uint32_t n) {
    asm volatile("mbarrier.init.shared.b64 [%0], %1;" :: "r"(a), "r"(n) : "memory");
}
__device__ __forceinline__ void mbar_expect(uint32_t a, uint32_t bytes) {
    asm volatile("mbarrier.arrive.expect_tx.shared.b64 _, [%0], %1;" :: "r"(a), "r"(bytes) : "memory");
}
__device__ __forceinline__ void bulk_g2s(uint32_t dst, const void* src, uint32_t bytes, uint32_t mbar) {
    asm volatile("cp.async.bulk.shared::cluster.global.mbarrier::complete_tx::bytes [%0], [%1], %2, [%3];"
                 :: "r"(dst), "l"(src), "r"(bytes), "r"(mbar) : "memory");
}
__device__ __forceinline__ void mbar_wait(uint32_t a, uint32_t parity) {
    asm volatile(
        "{\n\t.reg .pred P;\n"
        "W_%=:\n\t"
        "mbarrier.try_wait.parity.acquire.cta.shared::cta.b64 P, [%0], %1, 0x989680;\n\t"
        "@P bra.uni D_%=;\n\t"
        "bra.uni W_%=;\n"
        "D_%=:\n\t}"
        :: "r"(a), "r"(parity) : "memory");
}

// ---------------- phase 1: K/V projection (R8 verbatim) ----------------
#define ETILE 32
#define NSTAGE (DEMB / ETILE)     // 24
#define NBUF 3
#define WBUF_FLOATS (ETILE*DK*2)  // 16384 floats
#define EST_OFF (NBUF*WBUF_FLOATS)        // 49152
#define DYN_BYTES ((EST_OFF + DEMB*8) * 4)   // 221184 B

__device__ __forceinline__ void kv_phase(float* dynkv, unsigned long long* mb,
                     const float* __restrict__ emb,
                     const float* __restrict__ Wk, const float* __restrict__ bk,
                     const float* __restrict__ Wv, const float* __restrict__ bv,
                     int T)
{
    float* wbuf = dynkv;
    float* est  = dynkv + EST_OFF;

    const int tid = threadIdx.x;
    const int r0  = blockIdx.x * 8;
    const int rows = min(8, T - r0);
    const uint32_t wbufb = smem_u32(wbuf);
    const int s0 = blockIdx.x % NSTAGE;

    for (int idx = tid; idx < 8*DEMB; idx += 256) {
        int r = idx / DEMB, e = idx - r*DEMB;
        est[e*8 + r] = (r < rows) ? emb[(r0 + r)*DEMB + e] : 0.f;
    }
    if (tid == 0) {
        #pragma unroll
        for (int i = 0; i < NBUF; i++) mbar_init(smem_u32(&mb[i]), 1);
    }
    __syncthreads();

    auto issue = [&](int i) {
        int s = s0 + i; if (s >= NSTAGE) s -= NSTAGE;
        int buf = i % NBUF;
        uint32_t mba = smem_u32(&mb[buf]);
        uint32_t dst = wbufb + (uint32_t)buf * (WBUF_FLOATS*4u);
        mbar_expect(mba, WBUF_FLOATS*4u);
        bulk_g2s(dst,               Wk + s*ETILE*DK, ETILE*DK*4u, mba);
        bulk_g2s(dst + ETILE*DK*4u, Wv + s*ETILE*DK, ETILE*DK*4u, mba);
    };
    if (tid == 0) { issue(0); issue(1); issue(2); }

    unsigned long long aK[4], aV[4];
    #pragma unroll
    for (int p = 0; p < 4; p++) { aK[p] = pack2(0.f, 0.f); aV[p] = pack2(0.f, 0.f); }

    for (int i = 0; i < NSTAGE; i++) {
        int s = s0 + i; if (s >= NSTAGE) s -= NSTAGE;
        mbar_wait(smem_u32(&mb[i % NBUF]), (i / NBUF) & 1);
        const float* Wks = wbuf + (i % NBUF) * WBUF_FLOATS;
        const float* Wvs = Wks + ETILE*DK;
        const int e0 = s * ETILE;

        #pragma unroll 16
        for (int ee = 0; ee < ETILE; ee++) {
            float wk = Wks[ee*DK + tid];
            float wv = Wvs[ee*DK + tid];
            unsigned long long wk2 = pack2(wk, wk);
            unsigned long long wv2 = pack2(wv, wv);
            const float* ep = &est[(e0 + ee)*8];
            ulonglong2 p01 = *(const ulonglong2*)ep;
            ulonglong2 p23 = *(const ulonglong2*)(ep + 4);
            aK[0] = fma2(p01.x, wk2, aK[0]);  aV[0] = fma2(p01.x, wv2, aV[0]);
            aK[1] = fma2(p01.y, wk2, aK[1]);  aV[1] = fma2(p01.y, wv2, aV[1]);
            aK[2] = fma2(p23.x, wk2, aK[2]);  aV[2] = fma2(p23.x, wv2, aV[2]);
            aK[3] = fma2(p23.y, wk2, aK[3]);  aV[3] = fma2(p23.y, wv2, aV[3]);
        }
        __syncthreads();
        if (tid == 0 && i + NBUF < NSTAGE) issue(i + NBUF);
    }

    float bkv = bk[tid], bvv = bv[tid];
    #pragma unroll
    for (int p = 0; p < 4; p++) {
        float k0,k1,v0,v1;
        unpack2(aK[p], k0, k1);
        unpack2(aV[p], v0, v1);
        int r = 2*p;
        if (r < rows)     { g_K[(r0+r  )*DK + tid] = k0 + bkv; g_V[(r0+r  )*DK + tid] = v0 + bvv; }
        if (r + 1 < rows) { g_K[(r0+r+1)*DK + tid] = k1 + bkv; g_V[(r0+r+1)*DK + tid] = v1 + bvv; }
    }
}

// ---------------- phase 2: prep (R8 verbatim) ----------------
__device__ __forceinline__ void prep_phase(float* dyn, int cid,
                                           int T, int P, int nchS, int nchP)
{
    float* ks  = dyn;             // 32*260
    float* vs  = dyn + 8320;      // 32*260 (para only)
    float* Gs  = dyn + 16640;     // 32*33
    float* Ts  = dyn + 17696;     // 32*36
    float* Pm  = dyn + 18848;
    float* fs  = dyn + 18880;
    float* lfs = dyn + 18912;

    const int tid = threadIdx.x;
    const int wid = tid >> 5, lane = tid & 31;

    int type, chunk, steps;
    if (cid < nchS)              { type = 0; chunk = cid;               steps = T; }
    else if (cid < nchS + nchP)  { type = 1; chunk = cid - nchS;        steps = P; }
    else                         { type = 2; chunk = cid - nchS - nchP; steps = P; }
    const int lo  = chunk * CH;
    const int len = min(CH, steps - lo);
    const bool bwd = (type <= 1);
    const bool isPara = (type >= 1);

    if (!isPara) {
        #pragma unroll
        for (int u = 0; u < 8; u++) {
            int id = tid + 256*u;
            int a = id >> 6, c4 = (id & 63) * 4;
            float4 v = make_float4(0.f, 0.f, 0.f, 0.f);
            if (a < len) v = *(const float4*)&g_K[(lo + a)*DK + c4];
            *(float4*)&ks[a*260 + c4] = v;
        }
    } else {
        #pragma unroll
        for (int g = 0; g < 8; g++) {
            int r  = (tid >> 6) + 4*g;
            int c4 = (tid & 63) * 4;
            float4 ak = make_float4(0.f,0.f,0.f,0.f);
            float4 av = make_float4(0.f,0.f,0.f,0.f);
            if (r < len) {
                #pragma unroll
                for (int i = 0; i < 5; i++) {
                    float4 kk = *(const float4*)&g_K[((lo + r)*5 + i)*DK + c4];
                    float4 vv = *(const float4*)&g_V[((lo + r)*5 + i)*DK + c4];
                    ak.x += kk.x; ak.y += kk.y; ak.z += kk.z; ak.w += kk.w;
                    av.x += vv.x; av.y += vv.y; av.z += vv.z; av.w += vv.w;
                }
                ak.x *= 0.2f; ak.y *= 0.2f; ak.z *= 0.2f; ak.w *= 0.2f;
                av.x *= 0.2f; av.y *= 0.2f; av.z *= 0.2f; av.w *= 0.2f;
                if (type == 1) *(float4*)&g_PV[(lo + r)*DK + c4] = av;
            }
            *(float4*)&ks[r*260 + c4] = ak;
            *(float4*)&vs[r*260 + c4] = av;
        }
    }
    __syncthreads();

    if (type == 2) {
        #pragma unroll
        for (int rr = 0; rr < 4; rr++) {
            int r = wid*4 + rr;
            float s = 0.f;
            #pragma unroll
            for (int m = 0; m < 8; m++) s += vs[r*260 + lane + 32*m];
            #pragma unroll
            for (int o = 16; o; o >>= 1) s += __shfl_xor_sync(0xffffffffu, s, o);
            if (lane == 0) Pm[r] = s * (1.f/256.f);
        }
    }

    {
        float* gout = isPara ? g_PK : g_Kn;
        const bool wr = (type != 2);
        #pragma unroll
        for (int rr = 0; rr < 4; rr++) {
            int r = wid*4 + rr;
            float v[8]; float s = 0.f;
            #pragma unroll
            for (int m = 0; m < 8; m++) { v[m] = ks[r*260 + lane + 32*m]; s += v[m]*v[m]; }
            #pragma unroll
            for (int o = 16; o; o >>= 1) s += __shfl_xor_sync(0xffffffffu, s, o);
            float rinv = 1.f / fmaxf(sqrtf(s), EPSN);
            #pragma unroll
            for (int m = 0; m < 8; m++) {
                float nv = v[m] * rinv;
                ks[r*260 + lane + 32*m] = nv;
                if (wr && r < len) gout[(lo + r)*DK + lane + 32*m] = nv;
            }
        }
    }
    __syncthreads();

    {
        float acc[4] = {0.f, 0.f, 0.f, 0.f};
        #pragma unroll 8
        for (int i4 = 0; i4 < 64; i4++) {
            float4 own = *(const float4*)&ks[lane*260 + i4*4];
            #pragma unroll
            for (int s = 0; s < 4; s++) {
                float4 b = *(const float4*)&ks[(wid + 8*s)*260 + i4*4];
                acc[s] += own.x*b.x + own.y*b.y + own.z*b.z + own.w*b.w;
            }
        }
        #pragma unroll
        for (int s = 0; s < 4; s++) Gs[(wid + 8*s)*33 + lane] = acc[s];
    }
    __syncthreads();

    #pragma unroll
    for (int cc = 0; cc < 4; cc++) {
        int k = wid*4 + cc;
        float v = (lane == k) ? 1.f : 0.f;
        for (int i = 0; i < len; i++) {
            float vi = __shfl_sync(0xffffffffu, v, i);
            if (lane > i && lane < len) {
                float g = bwd ? Gs[(len-1-lane)*33 + (len-1-i)]
                              : Gs[lane*33 + i];
                v -= ALPHA * g * vi;
            }
        }
        Ts[lane*36 + k] = v;
    }
    __syncthreads();

    if (type == 2 && wid == 0) {
        float f = 0.f;
        if (lane < len) {
            float dp = 1.f;
            for (int i = 0; i <= lane; i++) dp *= (1.f / P_DECAY);
            f = BETA * dp * Pm[lane];
        }
        fs[lane] = f;
        __syncwarp();
        float lf = 0.f;
        if (lane < len)
            for (int i = 0; i < lane; i++) lf += Gs[lane*33 + i] * fs[i];
        lfs[lane] = lf;
        __syncwarp();
        float e = 0.f;
        #pragma unroll 8
        for (int k2 = 0; k2 < CH; k2++) e += Ts[lane*36 + k2] * lfs[k2];
        g_c[chunk*CH + lane] = -ALPHA * e + f;
    }

    float ksv[CH];
    #pragma unroll
    for (int m = 0; m < CH; m++) {
        int rl = bwd ? (len - 1 - m) : m;
        ksv[m] = (m < len) ? ks[rl*260 + tid] : 0.f;
    }
    float* Wout = g_W + (size_t)cid * CH * DK;
    #pragma unroll
    for (int j = 0; j < CH; j++) {
        float acc2 = 0.f;
        #pragma unroll
        for (int m4 = 0; m4 < 8; m4++) {
            float4 t = *(const float4*)&Ts[j*36 + m4*4];
            acc2 += t.x*ksv[m4*4] + t.y*ksv[m4*4+1] + t.z*ksv[m4*4+2] + t.w*ksv[m4*4+3];
        }
        Wout[j*DK + tid] = acc2;
    }
}

// ---------------- phase 3: scan (R8 verbatim) + final in block 0 ----------------
__device__ __forceinline__ float bred256(float x, float* red)
{
    const int tid = threadIdx.x;
    #pragma unroll
    for (int o = 16; o; o >>= 1) x += __shfl_xor_sync(0xffffffffu, x, o);
    __syncthreads();
    if ((tid & 31) == 0) red[tid >> 5] = x;
    __syncthreads();
    float s = 0.f;
    #pragma unroll
    for (int w = 0; w < 8; w++) s += red[w];
    return s;
}

__device__ __forceinline__ void scan_phase(float* dyn, int bid,
                                           const float* __restrict__ q,
                                           float* __restrict__ out,
                                           int T, int P, int nchS, int nchP)
{
    float* a_s    = dyn;            // 256
    float* sigk_s = dyn + 256;      // 32
    float* sigv_s = dyn + 288;      // 32
    float* dpow   = dyn + 320;      // 33
    float* red    = dyn + 356;      // 8
    float* s_invp = dyn + 364;      // 1

    const int tid = threadIdx.x;
    const int wid = tid >> 5, lane = tid & 31;
    const bool fwd  = (bid == 3);
    const bool sent = (bid == 0);
    const float decay = sent ? S_DECAY : P_DECAY;
    const int nch   = sent ? nchS : nchP;
    const int steps = sent ? T : P;
    const float* Kd = sent ? g_Kn : g_PK;
    const float* Vd = sent ? g_V  : g_PV;
    const int slot0 = sent ? 0 : (fwd ? (nchS + nchP) : nchS);

    if (tid == 0) {
        dpow[0] = 1.f;
        for (int i = 0; i < CH; i++) dpow[i+1] = dpow[i] * decay;
    }
    __syncthreads();

    float qv = q[tid];
    float a;
    {
        float x = qv * qv;
        #pragma unroll
        for (int o = 16; o; o >>= 1) x += __shfl_xor_sync(0xffffffffu, x, o);
        if (lane == 0) red[wid] = x;
        __syncthreads();
        if (tid == 0) {
            float s = 0.f;
            #pragma unroll
            for (int w = 0; w < 8; w++) s += red[w];
            *s_invp = 1.f / fmaxf(sqrtf(s), EPSN);
        }
        __syncthreads();
    }
    float s_inv = *s_invp;
    if (bid <= 1)      a = qv * s_inv;
    else if (bid == 2) a = 1.f/256.f;
    else               a = 0.f;
    a_s[tid] = a;

    const int j0 = wid * 4;
    float wreg[4][8];
    float creg[4] = {0.f, 0.f, 0.f, 0.f};

    {
        int chunk = fwd ? 0 : (nch - 1);
        const float* Wp = g_W + (size_t)(slot0 + chunk) * CH * DK;
        #pragma unroll
        for (int r = 0; r < 4; r++)
            #pragma unroll
            for (int m = 0; m < 8; m++)
                wreg[r][m] = Wp[(j0 + r)*DK + lane + 32*m];
        if (fwd) {
            #pragma unroll
            for (int r = 0; r < 4; r++) creg[r] = g_c[chunk*CH + j0 + r];
        }
    }

    float outreg = 0.f;

    for (int c = 0; c < nch; c++) {
        const int chunk = fwd ? c : (nch - 1 - c);
        const int lo  = chunk * CH;
        const int len = min(CH, steps - lo);
        const int hi  = lo + len - 1;
        __syncthreads();

        float kreg[CH], vreg[CH];
        #pragma unroll
        for (int j = 0; j < CH; j++) {
            int row = fwd ? (lo + j) : (hi - j);
            row = max(0, min(row, steps - 1));
            kreg[j] = Kd[row*DK + tid];
            vreg[j] = fwd ? 0.f : Vd[row*DK + tid];
        }

        float av[8];
        #pragma unroll
        for (int m = 0; m < 8; m++) av[m] = a_s[lane + 32*m];
        float s[4];
        #pragma unroll
        for (int r = 0; r < 4; r++) {
            float t = 0.f;
            #pragma unroll
            for (int m = 0; m < 8; m++) t += wreg[r][m] * av[m];
            s[r] = t;
        }
        #pragma unroll
        for (int o = 16; o; o >>= 1)
            #pragma unroll
            for (int r = 0; r < 4; r++)
                s[r] += __shfl_xor_sync(0xffffffffu, s[r], o);
        if (lane == 0) {
            #pragma unroll
            for (int r = 0; r < 4; r++) {
                int j = j0 + r;
                float sk = 0.f, sv = 0.f;
                if (j < len) {
                    if (fwd) { sk = -ALPHA * s[r] + creg[r]; }
                    else     { sk = -ALPHA * s[r]; sv = BETA * dpow[j] * s[r]; }
                }
                sigk_s[j] = sk;
                sigv_s[j] = sv;
            }
        }

        if (c + 1 < nch) {
            int nchunk = fwd ? (c + 1) : (nch - 2 - c);
            const float* Wp = g_W + (size_t)(slot0 + nchunk) * CH * DK;
            #pragma unroll
            for (int r = 0; r < 4; r++)
                #pragma unroll
                for (int m = 0; m < 8; m++)
                    wreg[r][m] = Wp[(j0 + r)*DK + lane + 32*m];
            if (fwd) {
                #pragma unroll
                for (int r = 0; r < 4; r++) creg[r] = g_c[nchunk*CH + j0 + r];
            }
        }
        __syncthreads();

        float wsum = 0.f, osum = 0.f;
        #pragma unroll
        for (int j = 0; j < CH; j++) {
            wsum += sigk_s[j] * kreg[j];
            osum += sigv_s[j] * vreg[j];
        }
        outreg += osum;
        a = dpow[len] * (a + wsum);
        a_s[tid] = a;
    }

    if (bid != 0) {
        if (bid < 3) g_res[bid*DK + tid] = outreg;
        else         g_res[3*DK + tid]   = a;
        __threadfence();
        __syncthreads();
        if (tid == 0) atomicAdd(&g_done, 1);
        return;
    }

    // ---- block 0: wait for blocks 1..3, then final combine ----
    if (tid == 0) {
        while (*(volatile int*)&g_done < 3) { }
    }
    __threadfence();
    __syncthreads();

    float r1  = g_res[1*DK + tid];
    float r2  = g_res[2*DK + tid];
    float dkv = g_res[3*DK + tid];
    float ssd = bred256(dkv*dkv, red);
    float dot = bred256(qv*dkv, red);
    float coef = dot * s_inv / fmaxf(sqrtf(ssd), EPSN);
    out[tid] = 0.2f*outreg + 0.3f*r1 + 0.5f*(BETA*coef)*r2;

    __syncthreads();
    // reset all inter-block state for the next graph replay
    for (int i = tid; i < 128; i += 256) g_kvdone[i] = 0;
    if (tid == 0) { g_bar2 = 0; g_done = 0; }
}

// ---------------- the single fused kernel ----------------
__global__ void __launch_bounds__(256, 1) k_mega(
                     const float* __restrict__ emb, const float* __restrict__ q,
                     const float* __restrict__ Wk, const float* __restrict__ bk,
                     const float* __restrict__ Wv, const float* __restrict__ bv,
                     float* __restrict__ out,
                     int T, int P, int nchS, int nchP, int nKV, int nPrep)
{
    extern __shared__ __align__(16) float dyn[];
    __shared__ __align__(8) unsigned long long mb[NBUF];

    const int bid = blockIdx.x, tid = threadIdx.x;

    // ---- phase 1: K/V projection (all blocks) ----
    kv_phase(dyn, mb, emb, Wk, bk, Wv, bv, T);

    // release own flag
    __threadfence();
    __syncthreads();
    if (tid == 0) atomicExch(&g_kvdone[bid], 1);
    if (bid >= nPrep) return;

    // fine-grained wait: only the kv blocks that produced THIS chunk's rows
    {
        int r0, r1;
        if (bid < nchS) { r0 = bid * CH; r1 = r0 + min(CH, T - r0) - 1; }
        else {
            int chunk = (bid < nchS + nchP) ? (bid - nchS) : (bid - nchS - nchP);
            int lo = chunk * CH;
            int len = min(CH, P - lo);
            r0 = lo * 5; r1 = (lo + len) * 5 - 1;
        }
        int kb0 = r0 >> 3, kb1 = r1 >> 3;
        if (tid == 0) {
            for (int b = kb0; b <= kb1; b++)
                while (*(volatile int*)&g_kvdone[b] == 0) { }
        }
    }
    __threadfence();
    __syncthreads();

    // ---- phase 2: prep (blocks 0..nPrep-1) ----
    prep_phase(dyn, bid, T, P, nchS, nchP);

    // barrier 2: nPrep blocks
    __threadfence();
    __syncthreads();
    if (tid == 0) atomicAdd(&g_bar2, 1);
    if (bid >= 4) return;
    if (tid == 0) { while (*(volatile int*)&g_bar2 < nPrep) { } }
    __threadfence();
    __syncthreads();

    // ---- phase 3: scans + final (blocks 0..3) ----
    scan_phase(dyn, bid, q, out, T, P, nchS, nchP);
}

// ---------------- launcher ----------------
extern "C" void kernel_launch(void* const* d_in, const int* in_sizes, int n_in,
                              void* d_out, int out_size)
{
    const float* emb = (const float*)d_in[0];
    const float* q   = (const float*)d_in[1];
    const float* Wk  = (const float*)d_in[2];
    const float* bk  = (const float*)d_in[3];
    const float* Wv  = (const float*)d_in[4];
    const float* bv  = (const float*)d_in[5];
    // d_in[6..8] = zero initial memories (collapsed analytically)

    int T = in_sizes[0] / DEMB;     // 1000
    int P = T / 5;                  // 200
    int nchS = (T + CH - 1) / CH;   // 32
    int nchP = (P + CH - 1) / CH;   // 7
    int nKV  = (T + 7) / 8;         // 125 (single wave, all co-resident)
    int nPrep = nchS + 2*nchP;      // 46

    cudaFuncSetAttribute(k_mega, cudaFuncAttributeMaxDynamicSharedMemorySize, DYN_BYTES);

    k_mega<<<nKV, 256, DYN_BYTES>>>(emb, q, Wk, bk, Wv, bv, (float*)d_out,
                                    T, P, nchS, nchP, nKV, nPrep);
}